// round 1
// baseline (speedup 1.0000x reference)
#include <cuda_runtime.h>
#include <math.h>

#define B_   2
#define L_   2048
#define DM   1024
#define DI   2048
#define DS   16
#define TOK  (B_*L_)

// ---------------- scratch (device globals; no allocs allowed) ----------------
__device__ float g_xn[TOK * DM];          // layernorm output
__device__ float g_xz[TOK * 2 * DI];      // in-proj output [token][4096] (x_part | z)
__device__ float g_xconv[TOK * DI];       // conv + silu output
__device__ float g_dt[TOK * DI];          // softplus(dt)
__device__ float g_BC[TOK * 2 * DS];      // [token][32]: cols 0..15 = B, 16..31 = C
__device__ float g_y[TOK * DI];           // scan output (gated)
__device__ float g_A[DI * DS];            // A = -exp(A_log)

// ---------------- helpers ----------------
__inline__ __device__ float warpsum(float v) {
    #pragma unroll
    for (int m = 16; m; m >>= 1) v += __shfl_xor_sync(0xffffffffu, v, m);
    return v;
}

// ---------------- layernorm ----------------
__global__ void ln_kernel(const float* __restrict__ x, const float* __restrict__ w,
                          const float* __restrict__ b, float* __restrict__ out) {
    int t = blockIdx.x;
    int tid = threadIdx.x;
    const float* xr = x + (size_t)t * DM;
    float s = 0.f, sq = 0.f;
    for (int i = tid; i < DM; i += 256) { float v = xr[i]; s += v; sq += v * v; }
    s = warpsum(s); sq = warpsum(sq);
    __shared__ float sh0[8], sh1[8];
    int wi = tid >> 5, l = tid & 31;
    if (l == 0) { sh0[wi] = s; sh1[wi] = sq; }
    __syncthreads();
    if (wi == 0) {
        s  = (l < 8) ? sh0[l] : 0.f;
        sq = (l < 8) ? sh1[l] : 0.f;
        s = warpsum(s); sq = warpsum(sq);
        if (l == 0) { sh0[0] = s; sh1[0] = sq; }
    }
    __syncthreads();
    float mu  = sh0[0] * (1.f / DM);
    float var = sh1[0] * (1.f / DM) - mu * mu;
    float r = rsqrtf(var + 1e-5f);
    for (int i = tid; i < DM; i += 256)
        out[(size_t)t * DM + i] = (xr[i] - mu) * r * w[i] + b[i];
}

// ---------------- A = -exp(A_log) ----------------
__global__ void prep_A(const float* __restrict__ Al, float* __restrict__ A) {
    int i = blockIdx.x * blockDim.x + threadIdx.x;
    if (i < DI * DS) A[i] = -expf(Al[i]);
}

// ---------------- generic tiled SGEMM: C[M,N] = A[M,K] @ B[N,K]^T (+epilogue) ----------------
// EPI: 0 = none, 1 = softplus(v + aux[col]), 2 = v + aux[idx] (residual)
// BCAT: B rows 0..15 from Bp, 16..31 from Bp2 (for concat(W_B, W_C))
template<int BM, int BN, int BK, int TM, int TN, int EPI, bool BCAT>
__global__ void __launch_bounds__(256) sgemm_kernel(
    const float* __restrict__ A, const float* __restrict__ Bp, const float* __restrict__ Bp2,
    float* __restrict__ C, int M, int N, int K, const float* __restrict__ aux)
{
    constexpr int PAD = 4;
    __shared__ float As[BK][BM + PAD];
    __shared__ float Bs[BK][BN + PAD];
    int tid = threadIdx.x;
    int bm0 = blockIdx.y * BM;
    int bn0 = blockIdx.x * BN;
    constexpr int TX = BN / TN;
    int tx = tid % TX;
    int ty = tid / TX;

    float acc[TM][TN];
    #pragma unroll
    for (int i = 0; i < TM; i++)
        #pragma unroll
        for (int j = 0; j < TN; j++) acc[i][j] = 0.f;

    constexpr int AF4 = BM * BK / 4;
    constexpr int BF4 = BN * BK / 4;
    constexpr int KQ  = BK / 4;

    for (int k0 = 0; k0 < K; k0 += BK) {
        #pragma unroll
        for (int q = tid; q < AF4; q += 256) {
            int row = q / KQ, c = q % KQ;
            float4 f = *(const float4*)(A + (size_t)(bm0 + row) * K + k0 + 4 * c);
            As[4*c+0][row] = f.x; As[4*c+1][row] = f.y;
            As[4*c+2][row] = f.z; As[4*c+3][row] = f.w;
        }
        #pragma unroll
        for (int q = tid; q < BF4; q += 256) {
            int row = q / KQ, c = q % KQ;
            const float* src;
            if (BCAT) {
                int r = bn0 + row;
                src = (r < 16) ? (Bp + (size_t)r * K) : (Bp2 + (size_t)(r - 16) * K);
            } else {
                src = Bp + (size_t)(bn0 + row) * K;
            }
            float4 f = *(const float4*)(src + k0 + 4 * c);
            Bs[4*c+0][row] = f.x; Bs[4*c+1][row] = f.y;
            Bs[4*c+2][row] = f.z; Bs[4*c+3][row] = f.w;
        }
        __syncthreads();
        #pragma unroll
        for (int k = 0; k < BK; k++) {
            float a[TM], b[TN];
            #pragma unroll
            for (int i = 0; i < TM; i++) a[i] = As[k][ty * TM + i];
            #pragma unroll
            for (int j = 0; j < TN; j++) b[j] = Bs[k][tx * TN + j];
            #pragma unroll
            for (int i = 0; i < TM; i++)
                #pragma unroll
                for (int j = 0; j < TN; j++)
                    acc[i][j] = fmaf(a[i], b[j], acc[i][j]);
        }
        __syncthreads();
    }

    #pragma unroll
    for (int i = 0; i < TM; i++) {
        int row = bm0 + ty * TM + i;
        #pragma unroll
        for (int j = 0; j < TN; j++) {
            int col = bn0 + tx * TN + j;
            size_t idx = (size_t)row * N + col;
            float v = acc[i][j];
            if (EPI == 1) {
                v += aux[col];
                v = (v > 20.f) ? v : log1pf(__expf(v));   // softplus
            } else if (EPI == 2) {
                v += aux[idx];                             // residual
            }
            C[idx] = v;
        }
    }
}

// ---------------- causal depthwise conv (K=4) + SiLU ----------------
__global__ void conv_silu_kernel(const float* __restrict__ cw, const float* __restrict__ cb) {
    int idx = blockIdx.x * blockDim.x + threadIdx.x;
    if (idx >= TOK * DI) return;
    int token = idx / DI;
    int c = idx - token * DI;
    int b = token / L_;
    int t = token - b * L_;
    float sum = cb[c];
    #pragma unroll
    for (int k = 0; k < 4; k++) {
        int tt = t - 3 + k;
        if (tt >= 0)
            sum = fmaf(g_xz[((size_t)(b * L_ + tt)) * (2 * DI) + c], cw[c * 4 + k], sum);
    }
    float s = sum / (1.f + __expf(-sum));   // silu
    g_xconv[idx] = s;
}

// ---------------- selective scan ----------------
// thread = (b, d, n); 16 lanes (one d) reduce y over n via shfl; lane n==0 fuses +x*D and *silu(z)
__global__ void scan_kernel(const float* __restrict__ Dv) {
    int tid  = blockIdx.x * blockDim.x + threadIdx.x;
    int lane = tid & 31;
    int gw   = tid >> 5;                 // 0..2047
    int b    = gw >> 10;
    int dpair = gw & 1023;
    int n = lane & 15;
    int d = dpair * 2 + (lane >> 4);

    float a  = g_A[d * DS + n];
    float Dd = Dv[d];
    float h  = 0.f;

    const float* dtp = g_dt    + (size_t)b * L_ * DI + d;
    const float* xcp = g_xconv + (size_t)b * L_ * DI + d;
    const float* zp  = g_xz    + (size_t)b * L_ * (2 * DI) + DI + d;
    const float* Bpp = g_BC    + (size_t)b * L_ * 32 + n;
    const float* Cpp = Bpp + 16;
    float* yp = g_y + (size_t)b * L_ * DI + d;

    for (int t = 0; t < L_; t++) {
        float dtv = dtp[(size_t)t * DI];
        float xcv = xcp[(size_t)t * DI];
        float Bv  = Bpp[(size_t)t * 32];
        float Cv  = Cpp[(size_t)t * 32];
        float e = __expf(a * dtv);
        h = fmaf(h, e, xcv * dtv * Bv);
        float p = h * Cv;
        p += __shfl_xor_sync(0xffffffffu, p, 1);
        p += __shfl_xor_sync(0xffffffffu, p, 2);
        p += __shfl_xor_sync(0xffffffffu, p, 4);
        p += __shfl_xor_sync(0xffffffffu, p, 8);
        if (n == 0) {
            float zv = zp[(size_t)t * 2 * DI];
            float sig = zv / (1.f + __expf(-zv));
            yp[(size_t)t * DI] = (p + xcv * Dd) * sig;
        }
    }
}

// ---------------- launch ----------------
extern "C" void kernel_launch(void* const* d_in, const int* in_sizes, int n_in,
                              void* d_out, int out_size) {
    const float* x      = (const float*)d_in[0];
    const float* norm_w = (const float*)d_in[1];
    const float* norm_b = (const float*)d_in[2];
    const float* W_in   = (const float*)d_in[3];
    const float* conv_w = (const float*)d_in[4];
    const float* conv_b = (const float*)d_in[5];
    const float* W_dt   = (const float*)d_in[6];
    const float* b_dt   = (const float*)d_in[7];
    const float* W_B    = (const float*)d_in[8];
    const float* W_C    = (const float*)d_in[9];
    const float* Dv     = (const float*)d_in[10];
    const float* A_log  = (const float*)d_in[11];
    const float* W_out  = (const float*)d_in[12];
    float* out = (float*)d_out;

    float *p_xn, *p_xz, *p_xc, *p_dt, *p_bc, *p_y, *p_A;
    cudaGetSymbolAddress((void**)&p_xn, g_xn);
    cudaGetSymbolAddress((void**)&p_xz, g_xz);
    cudaGetSymbolAddress((void**)&p_xc, g_xconv);
    cudaGetSymbolAddress((void**)&p_dt, g_dt);
    cudaGetSymbolAddress((void**)&p_bc, g_BC);
    cudaGetSymbolAddress((void**)&p_y,  g_y);
    cudaGetSymbolAddress((void**)&p_A,  g_A);

    // 1. layernorm
    ln_kernel<<<TOK, 256>>>(x, norm_w, norm_b, p_xn);

    // 2. in-proj: xz[4096,4096] = xn[4096,1024] @ W_in[4096,1024]^T
    {
        dim3 grid((2 * DI) / 128, TOK / 128);
        sgemm_kernel<128,128,16,8,8,0,false><<<grid, 256>>>(p_xn, W_in, nullptr, p_xz,
                                                            TOK, 2 * DI, DM, nullptr);
    }

    // 3. conv + silu
    conv_silu_kernel<<<(TOK * DI) / 256, 256>>>(conv_w, conv_b);

    // 4a. dt = softplus(x_conv @ W_dt^T + b_dt)
    {
        dim3 grid(DI / 128, TOK / 128);
        sgemm_kernel<128,128,16,8,8,1,false><<<grid, 256>>>(p_xc, W_dt, nullptr, p_dt,
                                                            TOK, DI, DI, b_dt);
    }

    // 4b. [B|C] = x_conv @ concat(W_B, W_C)^T   -> [4096, 32]
    {
        dim3 grid(1, TOK / 32);
        sgemm_kernel<32,32,16,2,2,0,true><<<grid, 256>>>(p_xc, W_B, W_C, p_bc,
                                                         TOK, 2 * DS, DI, nullptr);
    }

    // 4c. A = -exp(A_log)
    prep_A<<<(DI * DS + 255) / 256, 256>>>(A_log, p_A);

    // 5. selective scan + gating (writes g_y)
    scan_kernel<<<(B_ * DI * DS) / 256, 256>>>(Dv);

    // 6. out = residual + y @ W_out^T
    {
        dim3 grid(DM / 128, TOK / 128);
        sgemm_kernel<128,128,16,8,8,2,false><<<grid, 256>>>(p_y, W_out, nullptr, out,
                                                            TOK, DM, DI, x);
    }
}

// round 5
// speedup vs baseline: 1.3830x; 1.3830x over previous
#include <cuda_runtime.h>
#include <math.h>
#include <stdint.h>

#define B_   2
#define L_   2048
#define DM   1024
#define DI   2048
#define DS   16
#define TOK  (B_*L_)
#define KCH  16            // split-K chunks for BC gemm
#define KCW  (DI / KCH)    // 128

// ---------------- scratch (device globals; no allocs allowed) ----------------
__device__ float g_xn[TOK * DM];
__device__ float g_xz[TOK * 2 * DI];
__device__ float g_xconv[TOK * DI];
__device__ float g_dt[TOK * DI];
__device__ float g_BC[TOK * 2 * DS];
__device__ float g_BCp[KCH][TOK * 2 * DS];   // split-K partials (8MB)
__device__ float g_y[TOK * DI];
__device__ float g_A[DI * DS];

// ---------------- helpers ----------------
__inline__ __device__ float warpsum(float v) {
    #pragma unroll
    for (int m = 16; m; m >>= 1) v += __shfl_xor_sync(0xffffffffu, v, m);
    return v;
}

#define RND_TF32(f) (__float_as_uint(f) + 0x1000u)   // round-to-nearest; mma ignores low 13 bits

__device__ __forceinline__ void mma_tf32(float* c, const uint32_t* a, const uint32_t* b) {
    asm volatile(
        "mma.sync.aligned.m16n8k8.row.col.f32.tf32.tf32.f32 "
        "{%0,%1,%2,%3}, {%4,%5,%6,%7}, {%8,%9}, {%0,%1,%2,%3};"
        : "+f"(c[0]), "+f"(c[1]), "+f"(c[2]), "+f"(c[3])
        : "r"(a[0]), "r"(a[1]), "r"(a[2]), "r"(a[3]), "r"(b[0]), "r"(b[1]));
}

// ======================================================================
//  mma.sync TF32 GEMM: C[M,N] = A[M,K] @ B[N,K]^T (+epilogue)
//  CTA 128x128, BK=16, 8 warps in 2x4, warp tile 64x32.
//  EPI: 0 none, 1 softplus(v+aux[col]), 2 v+aux[row*N+col]
// ======================================================================
template<int EPI>
__global__ void __launch_bounds__(256, 2)
gemm_mma_kernel(const float* __restrict__ A, const float* __restrict__ Bw,
                float* __restrict__ C, int M, int N, int K,
                const float* __restrict__ aux)
{
    __shared__ float As[2][16][132];
    __shared__ float Bs[2][16][132];

    const int tid  = threadIdx.x;
    const int lane = tid & 31;
    const int warp = tid >> 5;
    const int g    = lane >> 2;
    const int tig  = lane & 3;
    const int wm   = warp >> 2;          // 0..1
    const int wn   = warp & 3;           // 0..3
    const int bm0  = blockIdx.y * 128;
    const int bn0  = blockIdx.x * 128;

    float acc[4][4][4];
    #pragma unroll
    for (int i = 0; i < 4; i++)
        #pragma unroll
        for (int j = 0; j < 4; j++)
            #pragma unroll
            for (int q = 0; q < 4; q++) acc[i][j][q] = 0.f;

    const int r0 = tid >> 2;   // 0..63 (+64 for second half)
    const int kq = tid & 3;

    float4 ra[2], rb[2];

#define LDG_T(k0) do { \
    ra[0] = *(const float4*)(A  + (size_t)(bm0 + r0)      * K + (k0) + 4*kq); \
    ra[1] = *(const float4*)(A  + (size_t)(bm0 + r0 + 64) * K + (k0) + 4*kq); \
    rb[0] = *(const float4*)(Bw + (size_t)(bn0 + r0)      * K + (k0) + 4*kq); \
    rb[1] = *(const float4*)(Bw + (size_t)(bn0 + r0 + 64) * K + (k0) + 4*kq); \
} while (0)

#define STS_T(buf) do { \
    As[buf][4*kq+0][r0]    = __uint_as_float(RND_TF32(ra[0].x)); \
    As[buf][4*kq+1][r0]    = __uint_as_float(RND_TF32(ra[0].y)); \
    As[buf][4*kq+2][r0]    = __uint_as_float(RND_TF32(ra[0].z)); \
    As[buf][4*kq+3][r0]    = __uint_as_float(RND_TF32(ra[0].w)); \
    As[buf][4*kq+0][r0+64] = __uint_as_float(RND_TF32(ra[1].x)); \
    As[buf][4*kq+1][r0+64] = __uint_as_float(RND_TF32(ra[1].y)); \
    As[buf][4*kq+2][r0+64] = __uint_as_float(RND_TF32(ra[1].z)); \
    As[buf][4*kq+3][r0+64] = __uint_as_float(RND_TF32(ra[1].w)); \
    Bs[buf][4*kq+0][r0]    = __uint_as_float(RND_TF32(rb[0].x)); \
    Bs[buf][4*kq+1][r0]    = __uint_as_float(RND_TF32(rb[0].y)); \
    Bs[buf][4*kq+2][r0]    = __uint_as_float(RND_TF32(rb[0].z)); \
    Bs[buf][4*kq+3][r0]    = __uint_as_float(RND_TF32(rb[0].w)); \
    Bs[buf][4*kq+0][r0+64] = __uint_as_float(RND_TF32(rb[1].x)); \
    Bs[buf][4*kq+1][r0+64] = __uint_as_float(RND_TF32(rb[1].y)); \
    Bs[buf][4*kq+2][r0+64] = __uint_as_float(RND_TF32(rb[1].z)); \
    Bs[buf][4*kq+3][r0+64] = __uint_as_float(RND_TF32(rb[1].w)); \
} while (0)

    const int n_iter = K >> 4;
    LDG_T(0);
    STS_T(0);
    __syncthreads();

    for (int it = 0; it < n_iter; it++) {
        const int cur = it & 1;
        if (it + 1 < n_iter) LDG_T((it + 1) << 4);

        #pragma unroll
        for (int ks = 0; ks < 2; ks++) {
            uint32_t af[4][4], bf[4][2];
            const int k0 = ks * 8 + tig;
            const int k1 = k0 + 4;
            #pragma unroll
            for (int i = 0; i < 4; i++) {
                const int row = wm * 64 + i * 16 + g;
                af[i][0] = __float_as_uint(As[cur][k0][row]);
                af[i][1] = __float_as_uint(As[cur][k0][row + 8]);
                af[i][2] = __float_as_uint(As[cur][k1][row]);
                af[i][3] = __float_as_uint(As[cur][k1][row + 8]);
            }
            #pragma unroll
            for (int j = 0; j < 4; j++) {
                const int col = wn * 32 + j * 8 + g;
                bf[j][0] = __float_as_uint(Bs[cur][k0][col]);
                bf[j][1] = __float_as_uint(Bs[cur][k1][col]);
            }
            #pragma unroll
            for (int i = 0; i < 4; i++)
                #pragma unroll
                for (int j = 0; j < 4; j++)
                    mma_tf32(acc[i][j], af[i], bf[j]);
        }
        __syncthreads();
        if (it + 1 < n_iter) {
            STS_T((it + 1) & 1);
        }
        __syncthreads();
    }

    // ---- epilogue: direct STG (float2 pairs) ----
    #pragma unroll
    for (int i = 0; i < 4; i++) {
        const int row = bm0 + wm * 64 + i * 16 + g;
        #pragma unroll
        for (int j = 0; j < 4; j++) {
            const int col = bn0 + wn * 32 + j * 8 + 2 * tig;
            #pragma unroll
            for (int half = 0; half < 2; half++) {
                const int r = row + half * 8;
                float v0 = acc[i][j][half * 2 + 0];
                float v1 = acc[i][j][half * 2 + 1];
                size_t idx = (size_t)r * N + col;
                if (EPI == 1) {
                    v0 += aux[col];
                    v1 += aux[col + 1];
                    v0 = (v0 > 20.f) ? v0 : log1pf(__expf(v0));
                    v1 = (v1 > 20.f) ? v1 : log1pf(__expf(v1));
                } else if (EPI == 2) {
                    v0 += aux[idx];
                    v1 += aux[idx + 1];
                }
                *(float2*)(C + idx) = make_float2(v0, v1);
            }
        }
    }
#undef LDG_T
#undef STS_T
}

// ---------------- layernorm ----------------
__global__ void ln_kernel(const float* __restrict__ x, const float* __restrict__ w,
                          const float* __restrict__ b, float* __restrict__ out) {
    int t = blockIdx.x;
    int tid = threadIdx.x;
    const float* xr = x + (size_t)t * DM;
    float s = 0.f, sq = 0.f;
    for (int i = tid; i < DM; i += 256) { float v = xr[i]; s += v; sq += v * v; }
    s = warpsum(s); sq = warpsum(sq);
    __shared__ float sh0[8], sh1[8];
    int wi = tid >> 5, l = tid & 31;
    if (l == 0) { sh0[wi] = s; sh1[wi] = sq; }
    __syncthreads();
    if (wi == 0) {
        s  = (l < 8) ? sh0[l] : 0.f;
        sq = (l < 8) ? sh1[l] : 0.f;
        s = warpsum(s); sq = warpsum(sq);
        if (l == 0) { sh0[0] = s; sh1[0] = sq; }
    }
    __syncthreads();
    float mu  = sh0[0] * (1.f / DM);
    float var = sh1[0] * (1.f / DM) - mu * mu;
    float r = rsqrtf(var + 1e-5f);
    for (int i = tid; i < DM; i += 256)
        out[(size_t)t * DM + i] = (xr[i] - mu) * r * w[i] + b[i];
}

// ---------------- A = -exp(A_log) ----------------
__global__ void prep_A(const float* __restrict__ Al, float* __restrict__ A) {
    int i = blockIdx.x * blockDim.x + threadIdx.x;
    if (i < DI * DS) A[i] = -expf(Al[i]);
}

// ---------------- BC split-K partial: 32x32 tile over K-chunk of 128 ----------------
__global__ void __launch_bounds__(256) bc_partial_kernel(
    const float* __restrict__ A, const float* __restrict__ Bp, const float* __restrict__ Bp2)
{
    constexpr int BM = 32, BN = 32, BK = 16, TM = 2, TN = 2;
    constexpr int PAD = 4;
    __shared__ float As[BK][BM + PAD];
    __shared__ float Bs[BK][BN + PAD];
    int tid = threadIdx.x;
    int kc  = blockIdx.x;                // 0..15
    int bm0 = blockIdx.y * BM;
    int kbeg = kc * KCW;
    constexpr int TX = BN / TN;
    int tx = tid % TX;
    int ty = tid / TX;

    float acc[TM][TN] = {};
    constexpr int AF4 = BM * BK / 4;
    constexpr int BF4 = BN * BK / 4;
    constexpr int KQ  = BK / 4;

    for (int k0 = kbeg; k0 < kbeg + KCW; k0 += BK) {
        #pragma unroll
        for (int q = tid; q < AF4; q += 256) {
            int row = q / KQ, c = q % KQ;
            float4 f = *(const float4*)(A + (size_t)(bm0 + row) * DI + k0 + 4 * c);
            As[4*c+0][row] = f.x; As[4*c+1][row] = f.y;
            As[4*c+2][row] = f.z; As[4*c+3][row] = f.w;
        }
        #pragma unroll
        for (int q = tid; q < BF4; q += 256) {
            int row = q / KQ, c = q % KQ;
            const float* src = (row < 16) ? (Bp + (size_t)row * DI) : (Bp2 + (size_t)(row - 16) * DI);
            float4 f = *(const float4*)(src + k0 + 4 * c);
            Bs[4*c+0][row] = f.x; Bs[4*c+1][row] = f.y;
            Bs[4*c+2][row] = f.z; Bs[4*c+3][row] = f.w;
        }
        __syncthreads();
        #pragma unroll
        for (int k = 0; k < BK; k++) {
            float a[TM], b[TN];
            #pragma unroll
            for (int i = 0; i < TM; i++) a[i] = As[k][ty * TM + i];
            #pragma unroll
            for (int j = 0; j < TN; j++) b[j] = Bs[k][tx * TN + j];
            #pragma unroll
            for (int i = 0; i < TM; i++)
                #pragma unroll
                for (int j = 0; j < TN; j++)
                    acc[i][j] = fmaf(a[i], b[j], acc[i][j]);
        }
        __syncthreads();
    }
    #pragma unroll
    for (int i = 0; i < TM; i++)
        #pragma unroll
        for (int j = 0; j < TN; j++)
            g_BCp[kc][(size_t)(bm0 + ty * TM + i) * 32 + tx * TN + j] = acc[i][j];
}

__global__ void bc_reduce_kernel() {
    int idx = blockIdx.x * blockDim.x + threadIdx.x;
    if (idx >= TOK * 32) return;
    float s = 0.f;
    #pragma unroll
    for (int kc = 0; kc < KCH; kc++) s += g_BCp[kc][idx];
    g_BC[idx] = s;
}

// ---------------- causal depthwise conv (K=4) + SiLU ----------------
__global__ void conv_silu_kernel(const float* __restrict__ cw, const float* __restrict__ cb) {
    int idx = blockIdx.x * blockDim.x + threadIdx.x;
    if (idx >= TOK * DI) return;
    int token = idx / DI;
    int c = idx - token * DI;
    int b = token / L_;
    int t = token - b * L_;
    float sum = cb[c];
    #pragma unroll
    for (int k = 0; k < 4; k++) {
        int tt = t - 3 + k;
        if (tt >= 0)
            sum = fmaf(g_xz[((size_t)(b * L_ + tt)) * (2 * DI) + c], cw[c * 4 + k], sum);
    }
    float s = sum / (1.f + __expf(-sum));
    g_xconv[idx] = s;
}

// ---------------- selective scan ----------------
__global__ void scan_kernel(const float* __restrict__ Dv) {
    int tid  = blockIdx.x * blockDim.x + threadIdx.x;
    int lane = tid & 31;
    int gw   = tid >> 5;
    int b    = gw >> 10;
    int dpair = gw & 1023;
    int n = lane & 15;
    int d = dpair * 2 + (lane >> 4);

    float a  = g_A[d * DS + n];
    float Dd = Dv[d];
    float h  = 0.f;

    const float* dtp = g_dt    + (size_t)b * L_ * DI + d;
    const float* xcp = g_xconv + (size_t)b * L_ * DI + d;
    const float* zp  = g_xz    + (size_t)b * L_ * (2 * DI) + DI + d;
    const float* Bpp = g_BC    + (size_t)b * L_ * 32 + n;
    const float* Cpp = Bpp + 16;
    float* yp = g_y + (size_t)b * L_ * DI + d;

    for (int t = 0; t < L_; t++) {
        float dtv = dtp[(size_t)t * DI];
        float xcv = xcp[(size_t)t * DI];
        float Bv  = Bpp[(size_t)t * 32];
        float Cv  = Cpp[(size_t)t * 32];
        float e = __expf(a * dtv);
        h = fmaf(h, e, xcv * dtv * Bv);
        float p = h * Cv;
        p += __shfl_xor_sync(0xffffffffu, p, 1);
        p += __shfl_xor_sync(0xffffffffu, p, 2);
        p += __shfl_xor_sync(0xffffffffu, p, 4);
        p += __shfl_xor_sync(0xffffffffu, p, 8);
        if (n == 0) {
            float zv = zp[(size_t)t * 2 * DI];
            float sig = zv / (1.f + __expf(-zv));
            yp[(size_t)t * DI] = (p + xcv * Dd) * sig;
        }
    }
}

// ---------------- launch ----------------
extern "C" void kernel_launch(void* const* d_in, const int* in_sizes, int n_in,
                              void* d_out, int out_size) {
    const float* x      = (const float*)d_in[0];
    const float* norm_w = (const float*)d_in[1];
    const float* norm_b = (const float*)d_in[2];
    const float* W_in   = (const float*)d_in[3];
    const float* conv_w = (const float*)d_in[4];
    const float* conv_b = (const float*)d_in[5];
    const float* W_dt   = (const float*)d_in[6];
    const float* b_dt   = (const float*)d_in[7];
    const float* W_B    = (const float*)d_in[8];
    const float* W_C    = (const float*)d_in[9];
    const float* Dv     = (const float*)d_in[10];
    const float* A_log  = (const float*)d_in[11];
    const float* W_out  = (const float*)d_in[12];
    float* out = (float*)d_out;

    float *p_xn, *p_xz, *p_xc, *p_dt, *p_y;
    cudaGetSymbolAddress((void**)&p_xn, g_xn);
    cudaGetSymbolAddress((void**)&p_xz, g_xz);
    cudaGetSymbolAddress((void**)&p_xc, g_xconv);
    cudaGetSymbolAddress((void**)&p_dt, g_dt);
    cudaGetSymbolAddress((void**)&p_y,  g_y);

    // 1. layernorm
    ln_kernel<<<TOK, 256>>>(x, norm_w, norm_b, p_xn);

    // 2. in-proj: xz = xn @ W_in^T    [4096 x 4096 x 1024]
    {
        dim3 grid((2 * DI) / 128, TOK / 128);
        gemm_mma_kernel<0><<<grid, 256>>>(p_xn, W_in, p_xz, TOK, 2 * DI, DM, nullptr);
    }

    // 3. conv + silu
    conv_silu_kernel<<<(TOK * DI) / 256, 256>>>(conv_w, conv_b);

    // 4a. dt = softplus(x_conv @ W_dt^T + b_dt)   [4096 x 2048 x 2048]
    {
        dim3 grid(DI / 128, TOK / 128);
        gemm_mma_kernel<1><<<grid, 256>>>(p_xc, W_dt, p_dt, TOK, DI, DI, b_dt);
    }

    // 4b. [B|C] split-K partials + reduce
    {
        dim3 grid(KCH, TOK / 32);
        bc_partial_kernel<<<grid, 256>>>(p_xc, W_B, W_C);
        bc_reduce_kernel<<<(TOK * 32 + 255) / 256, 256>>>();
    }

    // 4c. A = -exp(A_log)
    {
        float* p_A; cudaGetSymbolAddress((void**)&p_A, g_A);
        prep_A<<<(DI * DS + 255) / 256, 256>>>(A_log, p_A);
    }

    // 5. selective scan + gating
    scan_kernel<<<(B_ * DI * DS) / 256, 256>>>(Dv);

    // 6. out = residual + y @ W_out^T   [4096 x 1024 x 2048]
    {
        dim3 grid(DM / 128, TOK / 128);
        gemm_mma_kernel<2><<<grid, 256>>>(p_y, W_out, out, TOK, DM, DI, x);
    }
}

// round 8
// speedup vs baseline: 2.9852x; 2.1585x over previous
#include <cuda_runtime.h>
#include <math.h>
#include <stdint.h>

#define B_   2
#define L_   2048
#define DM   1024
#define DI   2048
#define DS   16
#define TOK  (B_*L_)
#define KCH  16            // split-K chunks for BC gemm
#define KCW  (DI / KCH)    // 128
#define CH   32            // scan time-chunk

// ---------------- scratch (device globals; no allocs allowed) ----------------
__device__ float g_xn[TOK * DM];
__device__ float g_xz[TOK * 2 * DI];
__device__ float g_xconv[TOK * DI];
__device__ float g_dt[TOK * DI];
__device__ float g_BC[TOK * 2 * DS];
__device__ float g_BCp[KCH][TOK * 2 * DS];   // split-K partials (8MB)
__device__ float g_y[TOK * DI];
__device__ float g_A[DI * DS];

// ---------------- helpers ----------------
__inline__ __device__ float warpsum(float v) {
    #pragma unroll
    for (int m = 16; m; m >>= 1) v += __shfl_xor_sync(0xffffffffu, v, m);
    return v;
}

#define RND_TF32(f) (__float_as_uint(f) + 0x1000u)   // round-to-nearest; mma ignores low 13 bits

__device__ __forceinline__ void mma_tf32(float* c, const uint32_t* a, const uint32_t* b) {
    asm volatile(
        "mma.sync.aligned.m16n8k8.row.col.f32.tf32.tf32.f32 "
        "{%0,%1,%2,%3}, {%4,%5,%6,%7}, {%8,%9}, {%0,%1,%2,%3};"
        : "+f"(c[0]), "+f"(c[1]), "+f"(c[2]), "+f"(c[3])
        : "r"(a[0]), "r"(a[1]), "r"(a[2]), "r"(a[3]), "r"(b[0]), "r"(b[1]));
}

// ======================================================================
//  mma.sync TF32 GEMM: C[M,N] = A[M,K] @ B[N,K]^T (+epilogue)
//  CTA 128x128, BK=16, 8 warps in 2x4, warp tile 64x32.
//  EPI: 0 none, 1 softplus(v+aux[col]), 2 v+aux[row*N+col]
// ======================================================================
template<int EPI>
__global__ void __launch_bounds__(256, 2)
gemm_mma_kernel(const float* __restrict__ A, const float* __restrict__ Bw,
                float* __restrict__ C, int M, int N, int K,
                const float* __restrict__ aux)
{
    __shared__ float As[2][16][132];
    __shared__ float Bs[2][16][132];

    const int tid  = threadIdx.x;
    const int lane = tid & 31;
    const int warp = tid >> 5;
    const int g    = lane >> 2;
    const int tig  = lane & 3;
    const int wm   = warp >> 2;          // 0..1
    const int wn   = warp & 3;           // 0..3
    const int bm0  = blockIdx.y * 128;
    const int bn0  = blockIdx.x * 128;

    float acc[4][4][4];
    #pragma unroll
    for (int i = 0; i < 4; i++)
        #pragma unroll
        for (int j = 0; j < 4; j++)
            #pragma unroll
            for (int q = 0; q < 4; q++) acc[i][j][q] = 0.f;

    const int r0 = tid >> 2;   // 0..63 (+64 for second half)
    const int kq = tid & 3;

    float4 ra[2], rb[2];

#define LDG_T(k0) do { \
    ra[0] = *(const float4*)(A  + (size_t)(bm0 + r0)      * K + (k0) + 4*kq); \
    ra[1] = *(const float4*)(A  + (size_t)(bm0 + r0 + 64) * K + (k0) + 4*kq); \
    rb[0] = *(const float4*)(Bw + (size_t)(bn0 + r0)      * K + (k0) + 4*kq); \
    rb[1] = *(const float4*)(Bw + (size_t)(bn0 + r0 + 64) * K + (k0) + 4*kq); \
} while (0)

#define STS_T(buf) do { \
    As[buf][4*kq+0][r0]    = __uint_as_float(RND_TF32(ra[0].x)); \
    As[buf][4*kq+1][r0]    = __uint_as_float(RND_TF32(ra[0].y)); \
    As[buf][4*kq+2][r0]    = __uint_as_float(RND_TF32(ra[0].z)); \
    As[buf][4*kq+3][r0]    = __uint_as_float(RND_TF32(ra[0].w)); \
    As[buf][4*kq+0][r0+64] = __uint_as_float(RND_TF32(ra[1].x)); \
    As[buf][4*kq+1][r0+64] = __uint_as_float(RND_TF32(ra[1].y)); \
    As[buf][4*kq+2][r0+64] = __uint_as_float(RND_TF32(ra[1].z)); \
    As[buf][4*kq+3][r0+64] = __uint_as_float(RND_TF32(ra[1].w)); \
    Bs[buf][4*kq+0][r0]    = __uint_as_float(RND_TF32(rb[0].x)); \
    Bs[buf][4*kq+1][r0]    = __uint_as_float(RND_TF32(rb[0].y)); \
    Bs[buf][4*kq+2][r0]    = __uint_as_float(RND_TF32(rb[0].z)); \
    Bs[buf][4*kq+3][r0]    = __uint_as_float(RND_TF32(rb[0].w)); \
    Bs[buf][4*kq+0][r0+64] = __uint_as_float(RND_TF32(rb[1].x)); \
    Bs[buf][4*kq+1][r0+64] = __uint_as_float(RND_TF32(rb[1].y)); \
    Bs[buf][4*kq+2][r0+64] = __uint_as_float(RND_TF32(rb[1].z)); \
    Bs[buf][4*kq+3][r0+64] = __uint_as_float(RND_TF32(rb[1].w)); \
} while (0)

    const int n_iter = K >> 4;
    LDG_T(0);
    STS_T(0);
    __syncthreads();

    for (int it = 0; it < n_iter; it++) {
        const int cur = it & 1;
        if (it + 1 < n_iter) LDG_T((it + 1) << 4);

        #pragma unroll
        for (int ks = 0; ks < 2; ks++) {
            uint32_t af[4][4], bf[4][2];
            const int k0 = ks * 8 + tig;
            const int k1 = k0 + 4;
            #pragma unroll
            for (int i = 0; i < 4; i++) {
                const int row = wm * 64 + i * 16 + g;
                af[i][0] = __float_as_uint(As[cur][k0][row]);
                af[i][1] = __float_as_uint(As[cur][k0][row + 8]);
                af[i][2] = __float_as_uint(As[cur][k1][row]);
                af[i][3] = __float_as_uint(As[cur][k1][row + 8]);
            }
            #pragma unroll
            for (int j = 0; j < 4; j++) {
                const int col = wn * 32 + j * 8 + g;
                bf[j][0] = __float_as_uint(Bs[cur][k0][col]);
                bf[j][1] = __float_as_uint(Bs[cur][k1][col]);
            }
            #pragma unroll
            for (int i = 0; i < 4; i++)
                #pragma unroll
                for (int j = 0; j < 4; j++)
                    mma_tf32(acc[i][j], af[i], bf[j]);
        }
        __syncthreads();
        if (it + 1 < n_iter) {
            STS_T((it + 1) & 1);
        }
        __syncthreads();
    }

    // ---- epilogue: direct STG (float2 pairs) ----
    #pragma unroll
    for (int i = 0; i < 4; i++) {
        const int row = bm0 + wm * 64 + i * 16 + g;
        #pragma unroll
        for (int j = 0; j < 4; j++) {
            const int col = bn0 + wn * 32 + j * 8 + 2 * tig;
            #pragma unroll
            for (int half = 0; half < 2; half++) {
                const int r = row + half * 8;
                float v0 = acc[i][j][half * 2 + 0];
                float v1 = acc[i][j][half * 2 + 1];
                size_t idx = (size_t)r * N + col;
                if (EPI == 1) {
                    v0 += aux[col];
                    v1 += aux[col + 1];
                    v0 = (v0 > 20.f) ? v0 : log1pf(__expf(v0));
                    v1 = (v1 > 20.f) ? v1 : log1pf(__expf(v1));
                } else if (EPI == 2) {
                    v0 += aux[idx];
                    v1 += aux[idx + 1];
                }
                *(float2*)(C + idx) = make_float2(v0, v1);
            }
        }
    }
#undef LDG_T
#undef STS_T
}

// ---------------- layernorm ----------------
__global__ void ln_kernel(const float* __restrict__ x, const float* __restrict__ w,
                          const float* __restrict__ b, float* __restrict__ out) {
    int t = blockIdx.x;
    int tid = threadIdx.x;
    const float* xr = x + (size_t)t * DM;
    float s = 0.f, sq = 0.f;
    for (int i = tid; i < DM; i += 256) { float v = xr[i]; s += v; sq += v * v; }
    s = warpsum(s); sq = warpsum(sq);
    __shared__ float sh0[8], sh1[8];
    int wi = tid >> 5, l = tid & 31;
    if (l == 0) { sh0[wi] = s; sh1[wi] = sq; }
    __syncthreads();
    if (wi == 0) {
        s  = (l < 8) ? sh0[l] : 0.f;
        sq = (l < 8) ? sh1[l] : 0.f;
        s = warpsum(s); sq = warpsum(sq);
        if (l == 0) { sh0[0] = s; sh1[0] = sq; }
    }
    __syncthreads();
    float mu  = sh0[0] * (1.f / DM);
    float var = sh1[0] * (1.f / DM) - mu * mu;
    float r = rsqrtf(var + 1e-5f);
    for (int i = tid; i < DM; i += 256)
        out[(size_t)t * DM + i] = (xr[i] - mu) * r * w[i] + b[i];
}

// ---------------- A = -exp(A_log) ----------------
__global__ void prep_A(const float* __restrict__ Al, float* __restrict__ A) {
    int i = blockIdx.x * blockDim.x + threadIdx.x;
    if (i < DI * DS) A[i] = -expf(Al[i]);
}

// ---------------- BC split-K partial: 32x32 tile over K-chunk of 128 ----------------
__global__ void __launch_bounds__(256) bc_partial_kernel(
    const float* __restrict__ A, const float* __restrict__ Bp, const float* __restrict__ Bp2)
{
    constexpr int BM = 32, BN = 32, BK = 16, TM = 2, TN = 2;
    constexpr int PAD = 4;
    __shared__ float As[BK][BM + PAD];
    __shared__ float Bs[BK][BN + PAD];
    int tid = threadIdx.x;
    int kc  = blockIdx.x;                // 0..15
    int bm0 = blockIdx.y * BM;
    int kbeg = kc * KCW;
    constexpr int TX = BN / TN;
    int tx = tid % TX;
    int ty = tid / TX;

    float acc[TM][TN] = {};
    constexpr int AF4 = BM * BK / 4;
    constexpr int BF4 = BN * BK / 4;
    constexpr int KQ  = BK / 4;

    for (int k0 = kbeg; k0 < kbeg + KCW; k0 += BK) {
        #pragma unroll
        for (int q = tid; q < AF4; q += 256) {
            int row = q / KQ, c = q % KQ;
            float4 f = *(const float4*)(A + (size_t)(bm0 + row) * DI + k0 + 4 * c);
            As[4*c+0][row] = f.x; As[4*c+1][row] = f.y;
            As[4*c+2][row] = f.z; As[4*c+3][row] = f.w;
        }
        #pragma unroll
        for (int q = tid; q < BF4; q += 256) {
            int row = q / KQ, c = q % KQ;
            const float* src = (row < 16) ? (Bp + (size_t)row * DI) : (Bp2 + (size_t)(row - 16) * DI);
            float4 f = *(const float4*)(src + k0 + 4 * c);
            Bs[4*c+0][row] = f.x; Bs[4*c+1][row] = f.y;
            Bs[4*c+2][row] = f.z; Bs[4*c+3][row] = f.w;
        }
        __syncthreads();
        #pragma unroll
        for (int k = 0; k < BK; k++) {
            float a[TM], b[TN];
            #pragma unroll
            for (int i = 0; i < TM; i++) a[i] = As[k][ty * TM + i];
            #pragma unroll
            for (int j = 0; j < TN; j++) b[j] = Bs[k][tx * TN + j];
            #pragma unroll
            for (int i = 0; i < TM; i++)
                #pragma unroll
                for (int j = 0; j < TN; j++)
                    acc[i][j] = fmaf(a[i], b[j], acc[i][j]);
        }
        __syncthreads();
    }
    #pragma unroll
    for (int i = 0; i < TM; i++)
        #pragma unroll
        for (int j = 0; j < TN; j++)
            g_BCp[kc][(size_t)(bm0 + ty * TM + i) * 32 + tx * TN + j] = acc[i][j];
}

__global__ void bc_reduce_kernel() {
    int idx = blockIdx.x * blockDim.x + threadIdx.x;
    if (idx >= TOK * 32) return;
    float s = 0.f;
    #pragma unroll
    for (int kc = 0; kc < KCH; kc++) s += g_BCp[kc][idx];
    g_BC[idx] = s;
}

// ---------------- causal depthwise conv (K=4) + SiLU ----------------
__global__ void conv_silu_kernel(const float* __restrict__ cw, const float* __restrict__ cb) {
    int idx = blockIdx.x * blockDim.x + threadIdx.x;
    if (idx >= TOK * DI) return;
    int token = idx / DI;
    int c = idx - token * DI;
    int b = token / L_;
    int t = token - b * L_;
    float sum = cb[c];
    #pragma unroll
    for (int k = 0; k < 4; k++) {
        int tt = t - 3 + k;
        if (tt >= 0)
            sum = fmaf(g_xz[((size_t)(b * L_ + tt)) * (2 * DI) + c], cw[c * 4 + k], sum);
    }
    float s = sum / (1.f + __expf(-sum));
    g_xconv[idx] = s;
}

// ======================================================================
//  selective scan, smem-staged & pipelined.
//  Block = 512 thr = 16 warps handles (batch b, 32 d-channels).
//  Warp w owns d-local {2w, 2w+1}; lane: n = lane&15, dl = 2w + (lane>>4).
//  Time processed in 64 chunks of CH=32; dt/xc/z/BC staged coalesced into
//  double-buffered smem; LDG prefetch of chunk c+1 overlaps scan of chunk c.
// ======================================================================
__global__ void __launch_bounds__(512) scan_kernel(const float* __restrict__ Dv) {
    __shared__ float s_dt[2][CH][32];
    __shared__ float s_xc[2][CH][32];
    __shared__ float s_z [2][CH][32];
    __shared__ float s_bc[2][CH][32];
    __shared__ float s_y [CH][32];

    const int tid  = threadIdx.x;
    const int warp = tid >> 5;
    const int lane = tid & 31;
    const int b    = blockIdx.x >> 6;            // 64 d-blocks per batch
    const int dblk = (blockIdx.x & 63) * 32;
    const int n    = lane & 15;
    const int dl   = 2 * warp + (lane >> 4);
    const int d    = dblk + dl;

    const float a  = g_A[d * DS + n];
    const float Dd = Dv[d];
    const size_t tok0 = (size_t)b * L_;

    float r_dt[2], r_xc[2], r_z[2], r_bc[2];

#define SCAN_LDG(t0) do { \
    _Pragma("unroll") \
    for (int e = 0; e < 2; e++) { \
        size_t tok = tok0 + (t0) + warp + 16 * e; \
        r_dt[e] = g_dt   [tok * DI + dblk + lane]; \
        r_xc[e] = g_xconv[tok * DI + dblk + lane]; \
        r_z [e] = g_xz   [tok * 2 * DI + DI + dblk + lane]; \
        r_bc[e] = g_BC   [tok * 32 + lane]; \
    } } while (0)

#define SCAN_STS(buf) do { \
    _Pragma("unroll") \
    for (int e = 0; e < 2; e++) { \
        int i = warp + 16 * e; \
        s_dt[buf][i][lane] = r_dt[e]; \
        s_xc[buf][i][lane] = r_xc[e]; \
        s_z [buf][i][lane] = r_z [e]; \
        s_bc[buf][i][lane] = r_bc[e]; \
    } } while (0)

    SCAN_LDG(0);
    SCAN_STS(0);
    __syncthreads();

    float h = 0.f;
    const int n_chunks = L_ / CH;     // 64

    for (int c = 0; c < n_chunks; c++) {
        if (c + 1 < n_chunks) SCAN_LDG((c + 1) * CH);
        const int cur = c & 1;

        #pragma unroll
        for (int i = 0; i < CH; i++) {
            float dtv = s_dt[cur][i][dl];
            float xcv = s_xc[cur][i][dl];
            float Bv  = s_bc[cur][i][n];
            float Cv  = s_bc[cur][i][16 + n];
            float e = __expf(a * dtv);
            h = fmaf(h, e, xcv * dtv * Bv);
            float p = h * Cv;
            p += __shfl_xor_sync(0xffffffffu, p, 1);
            p += __shfl_xor_sync(0xffffffffu, p, 2);
            p += __shfl_xor_sync(0xffffffffu, p, 4);
            p += __shfl_xor_sync(0xffffffffu, p, 8);
            if (n == 0) {
                float zv = s_z[cur][i][dl];
                float sig = zv / (1.f + __expf(-zv));
                s_y[i][dl] = (p + xcv * Dd) * sig;
            }
        }
        __syncthreads();   // scan reads + s_y writes done

        #pragma unroll
        for (int e = 0; e < 2; e++) {
            int i = warp + 16 * e;
            g_y[(tok0 + c * CH + i) * DI + dblk + lane] = s_y[i][lane];
        }
        if (c + 1 < n_chunks) SCAN_STS((c + 1) & 1);
        __syncthreads();   // next buffer ready; s_y drained
    }
#undef SCAN_LDG
#undef SCAN_STS
}

// ---------------- launch ----------------
extern "C" void kernel_launch(void* const* d_in, const int* in_sizes, int n_in,
                              void* d_out, int out_size) {
    const float* x      = (const float*)d_in[0];
    const float* norm_w = (const float*)d_in[1];
    const float* norm_b = (const float*)d_in[2];
    const float* W_in   = (const float*)d_in[3];
    const float* conv_w = (const float*)d_in[4];
    const float* conv_b = (const float*)d_in[5];
    const float* W_dt   = (const float*)d_in[6];
    const float* b_dt   = (const float*)d_in[7];
    const float* W_B    = (const float*)d_in[8];
    const float* W_C    = (const float*)d_in[9];
    const float* Dv     = (const float*)d_in[10];
    const float* A_log  = (const float*)d_in[11];
    const float* W_out  = (const float*)d_in[12];
    float* out = (float*)d_out;

    float *p_xn, *p_xz, *p_xc, *p_dt, *p_y;
    cudaGetSymbolAddress((void**)&p_xn, g_xn);
    cudaGetSymbolAddress((void**)&p_xz, g_xz);
    cudaGetSymbolAddress((void**)&p_xc, g_xconv);
    cudaGetSymbolAddress((void**)&p_dt, g_dt);
    cudaGetSymbolAddress((void**)&p_y,  g_y);

    // 1. layernorm
    ln_kernel<<<TOK, 256>>>(x, norm_w, norm_b, p_xn);

    // 2. in-proj: xz = xn @ W_in^T    [4096 x 4096 x 1024]
    {
        dim3 grid((2 * DI) / 128, TOK / 128);
        gemm_mma_kernel<0><<<grid, 256>>>(p_xn, W_in, p_xz, TOK, 2 * DI, DM, nullptr);
    }

    // 3. conv + silu
    conv_silu_kernel<<<(TOK * DI) / 256, 256>>>(conv_w, conv_b);

    // 4a. dt = softplus(x_conv @ W_dt^T + b_dt)   [4096 x 2048 x 2048]
    {
        dim3 grid(DI / 128, TOK / 128);
        gemm_mma_kernel<1><<<grid, 256>>>(p_xc, W_dt, p_dt, TOK, DI, DI, b_dt);
    }

    // 4b. [B|C] split-K partials + reduce
    {
        dim3 grid(KCH, TOK / 32);
        bc_partial_kernel<<<grid, 256>>>(p_xc, W_B, W_C);
        bc_reduce_kernel<<<(TOK * 32 + 255) / 256, 256>>>();
    }

    // 4c. A = -exp(A_log)
    {
        float* p_A; cudaGetSymbolAddress((void**)&p_A, g_A);
        prep_A<<<(DI * DS + 255) / 256, 256>>>(A_log, p_A);
    }

    // 5. selective scan + gating (smem-staged pipeline)
    scan_kernel<<<B_ * (DI / 32), 512>>>(Dv);

    // 6. out = residual + y @ W_out^T   [4096 x 1024 x 2048]
    {
        dim3 grid(DM / 128, TOK / 128);
        gemm_mma_kernel<2><<<grid, 256>>>(p_y, W_out, out, TOK, DM, DI, x);
    }
}

// round 9
// speedup vs baseline: 3.4183x; 1.1451x over previous
#include <cuda_runtime.h>
#include <math.h>
#include <stdint.h>

#define B_   2
#define L_   2048
#define DM   1024
#define DI   2048
#define DS   16
#define TOK  (B_*L_)
#define KCH  16            // split-K chunks for BC gemm
#define KCW  (DI / KCH)    // 128
#define CH   32            // scan time-chunk

// ---------------- scratch (device globals; no allocs allowed) ----------------
__device__ float g_xn[TOK * DM];
__device__ float g_xz[TOK * 2 * DI];
__device__ float g_xconv[TOK * DI];
__device__ float g_dt[TOK * DI];
__device__ float g_BC[TOK * 2 * DS];
__device__ float g_BCp[KCH][TOK * 2 * DS];   // split-K partials (8MB)
__device__ float g_y[TOK * DI];
__device__ float g_A[DI * DS];

// ---------------- helpers ----------------
__inline__ __device__ float warpsum(float v) {
    #pragma unroll
    for (int m = 16; m; m >>= 1) v += __shfl_xor_sync(0xffffffffu, v, m);
    return v;
}

#define RND_TF32(f) (__float_as_uint(f) + 0x1000u)   // round-to-nearest; mma ignores low 13 bits

__device__ __forceinline__ void mma_tf32(float* c, const uint32_t* a, const uint32_t* b) {
    asm volatile(
        "mma.sync.aligned.m16n8k8.row.col.f32.tf32.tf32.f32 "
        "{%0,%1,%2,%3}, {%4,%5,%6,%7}, {%8,%9}, {%0,%1,%2,%3};"
        : "+f"(c[0]), "+f"(c[1]), "+f"(c[2]), "+f"(c[3])
        : "r"(a[0]), "r"(a[1]), "r"(a[2]), "r"(a[3]), "r"(b[0]), "r"(b[1]));
}

// ======================================================================
//  mma.sync TF32 GEMM: C[M,N] = A[M,K] @ B[N,K]^T (+epilogue)
//  CTA 128x128, BK=16, 8 warps in 2x4, warp tile 64x32.
//  SMEM layout [m][k] (stride 20): STS.128 stores, conflict-free frag LDS.
//  EPI: 0 none, 1 softplus(v+aux[col]), 2 v+aux[row*N+col]
// ======================================================================
template<int EPI>
__global__ void __launch_bounds__(256, 2)
gemm_mma_kernel(const float* __restrict__ A, const float* __restrict__ Bw,
                float* __restrict__ C, int M, int N, int K,
                const float* __restrict__ aux)
{
    __shared__ float As[2][128][20];
    __shared__ float Bs[2][128][20];

    const int tid  = threadIdx.x;
    const int lane = tid & 31;
    const int warp = tid >> 5;
    const int g    = lane >> 2;
    const int tig  = lane & 3;
    const int wm   = warp >> 2;          // 0..1
    const int wn   = warp & 3;           // 0..3
    const int bm0  = blockIdx.y * 128;
    const int bn0  = blockIdx.x * 128;

    float acc[4][4][4];
    #pragma unroll
    for (int i = 0; i < 4; i++)
        #pragma unroll
        for (int j = 0; j < 4; j++)
            #pragma unroll
            for (int q = 0; q < 4; q++) acc[i][j][q] = 0.f;

    const int r0 = tid >> 2;   // 0..63 (+64 for second half)
    const int kq = tid & 3;    // k-quad: owns k = 4kq..4kq+3

    float4 ra[2], rb[2];

#define LDG_T(k0) do { \
    ra[0] = *(const float4*)(A  + (size_t)(bm0 + r0)      * K + (k0) + 4*kq); \
    ra[1] = *(const float4*)(A  + (size_t)(bm0 + r0 + 64) * K + (k0) + 4*kq); \
    rb[0] = *(const float4*)(Bw + (size_t)(bn0 + r0)      * K + (k0) + 4*kq); \
    rb[1] = *(const float4*)(Bw + (size_t)(bn0 + r0 + 64) * K + (k0) + 4*kq); \
} while (0)

#define STS_T(buf) do { \
    uint4 u; \
    u = make_uint4(RND_TF32(ra[0].x), RND_TF32(ra[0].y), RND_TF32(ra[0].z), RND_TF32(ra[0].w)); \
    *(uint4*)&As[buf][r0][4*kq] = u; \
    u = make_uint4(RND_TF32(ra[1].x), RND_TF32(ra[1].y), RND_TF32(ra[1].z), RND_TF32(ra[1].w)); \
    *(uint4*)&As[buf][r0 + 64][4*kq] = u; \
    u = make_uint4(RND_TF32(rb[0].x), RND_TF32(rb[0].y), RND_TF32(rb[0].z), RND_TF32(rb[0].w)); \
    *(uint4*)&Bs[buf][r0][4*kq] = u; \
    u = make_uint4(RND_TF32(rb[1].x), RND_TF32(rb[1].y), RND_TF32(rb[1].z), RND_TF32(rb[1].w)); \
    *(uint4*)&Bs[buf][r0 + 64][4*kq] = u; \
} while (0)

    const int n_iter = K >> 4;
    LDG_T(0);
    STS_T(0);
    __syncthreads();

    for (int it = 0; it < n_iter; it++) {
        const int cur = it & 1;
        if (it + 1 < n_iter) LDG_T((it + 1) << 4);

        #pragma unroll
        for (int ks = 0; ks < 2; ks++) {
            uint32_t af[4][4], bf[4][2];
            const int k0 = ks * 8 + tig;
            const int k1 = k0 + 4;
            #pragma unroll
            for (int i = 0; i < 4; i++) {
                const int row = wm * 64 + i * 16 + g;
                af[i][0] = __float_as_uint(As[cur][row][k0]);
                af[i][1] = __float_as_uint(As[cur][row + 8][k0]);
                af[i][2] = __float_as_uint(As[cur][row][k1]);
                af[i][3] = __float_as_uint(As[cur][row + 8][k1]);
            }
            #pragma unroll
            for (int j = 0; j < 4; j++) {
                const int col = wn * 32 + j * 8 + g;
                bf[j][0] = __float_as_uint(Bs[cur][col][k0]);
                bf[j][1] = __float_as_uint(Bs[cur][col][k1]);
            }
            #pragma unroll
            for (int i = 0; i < 4; i++)
                #pragma unroll
                for (int j = 0; j < 4; j++)
                    mma_tf32(acc[i][j], af[i], bf[j]);
        }
        // STS targets the buffer whose readers finished before the previous
        // barrier -> only ONE sync per iteration needed.
        if (it + 1 < n_iter) STS_T((it + 1) & 1);
        __syncthreads();
    }

    // ---- epilogue: direct STG (float2 pairs) ----
    #pragma unroll
    for (int i = 0; i < 4; i++) {
        const int row = bm0 + wm * 64 + i * 16 + g;
        #pragma unroll
        for (int j = 0; j < 4; j++) {
            const int col = bn0 + wn * 32 + j * 8 + 2 * tig;
            #pragma unroll
            for (int half = 0; half < 2; half++) {
                const int r = row + half * 8;
                float v0 = acc[i][j][half * 2 + 0];
                float v1 = acc[i][j][half * 2 + 1];
                size_t idx = (size_t)r * N + col;
                if (EPI == 1) {
                    v0 += aux[col];
                    v1 += aux[col + 1];
                    v0 = (v0 > 20.f) ? v0 : log1pf(__expf(v0));
                    v1 = (v1 > 20.f) ? v1 : log1pf(__expf(v1));
                } else if (EPI == 2) {
                    v0 += aux[idx];
                    v1 += aux[idx + 1];
                }
                *(float2*)(C + idx) = make_float2(v0, v1);
            }
        }
    }
#undef LDG_T
#undef STS_T
}

// ---------------- layernorm ----------------
__global__ void ln_kernel(const float* __restrict__ x, const float* __restrict__ w,
                          const float* __restrict__ b, float* __restrict__ out) {
    int t = blockIdx.x;
    int tid = threadIdx.x;
    const float* xr = x + (size_t)t * DM;
    float s = 0.f, sq = 0.f;
    for (int i = tid; i < DM; i += 256) { float v = xr[i]; s += v; sq += v * v; }
    s = warpsum(s); sq = warpsum(sq);
    __shared__ float sh0[8], sh1[8];
    int wi = tid >> 5, l = tid & 31;
    if (l == 0) { sh0[wi] = s; sh1[wi] = sq; }
    __syncthreads();
    if (wi == 0) {
        s  = (l < 8) ? sh0[l] : 0.f;
        sq = (l < 8) ? sh1[l] : 0.f;
        s = warpsum(s); sq = warpsum(sq);
        if (l == 0) { sh0[0] = s; sh1[0] = sq; }
    }
    __syncthreads();
    float mu  = sh0[0] * (1.f / DM);
    float var = sh1[0] * (1.f / DM) - mu * mu;
    float r = rsqrtf(var + 1e-5f);
    for (int i = tid; i < DM; i += 256)
        out[(size_t)t * DM + i] = (xr[i] - mu) * r * w[i] + b[i];
}

// ---------------- A = -exp(A_log) ----------------
__global__ void prep_A(const float* __restrict__ Al, float* __restrict__ A) {
    int i = blockIdx.x * blockDim.x + threadIdx.x;
    if (i < DI * DS) A[i] = -expf(Al[i]);
}

// ---------------- BC split-K partial: 32x32 tile over K-chunk of 128 ----------------
__global__ void __launch_bounds__(256) bc_partial_kernel(
    const float* __restrict__ A, const float* __restrict__ Bp, const float* __restrict__ Bp2)
{
    constexpr int BM = 32, BN = 32, BK = 16, TM = 2, TN = 2;
    constexpr int PAD = 4;
    __shared__ float As[BK][BM + PAD];
    __shared__ float Bs[BK][BN + PAD];
    int tid = threadIdx.x;
    int kc  = blockIdx.x;                // 0..15
    int bm0 = blockIdx.y * BM;
    int kbeg = kc * KCW;
    constexpr int TX = BN / TN;
    int tx = tid % TX;
    int ty = tid / TX;

    float acc[TM][TN] = {};
    constexpr int AF4 = BM * BK / 4;
    constexpr int BF4 = BN * BK / 4;
    constexpr int KQ  = BK / 4;

    for (int k0 = kbeg; k0 < kbeg + KCW; k0 += BK) {
        #pragma unroll
        for (int q = tid; q < AF4; q += 256) {
            int row = q / KQ, c = q % KQ;
            float4 f = *(const float4*)(A + (size_t)(bm0 + row) * DI + k0 + 4 * c);
            As[4*c+0][row] = f.x; As[4*c+1][row] = f.y;
            As[4*c+2][row] = f.z; As[4*c+3][row] = f.w;
        }
        #pragma unroll
        for (int q = tid; q < BF4; q += 256) {
            int row = q / KQ, c = q % KQ;
            const float* src = (row < 16) ? (Bp + (size_t)row * DI) : (Bp2 + (size_t)(row - 16) * DI);
            float4 f = *(const float4*)(src + k0 + 4 * c);
            Bs[4*c+0][row] = f.x; Bs[4*c+1][row] = f.y;
            Bs[4*c+2][row] = f.z; Bs[4*c+3][row] = f.w;
        }
        __syncthreads();
        #pragma unroll
        for (int k = 0; k < BK; k++) {
            float a[TM], b[TN];
            #pragma unroll
            for (int i = 0; i < TM; i++) a[i] = As[k][ty * TM + i];
            #pragma unroll
            for (int j = 0; j < TN; j++) b[j] = Bs[k][tx * TN + j];
            #pragma unroll
            for (int i = 0; i < TM; i++)
                #pragma unroll
                for (int j = 0; j < TN; j++)
                    acc[i][j] = fmaf(a[i], b[j], acc[i][j]);
        }
        __syncthreads();
    }
    #pragma unroll
    for (int i = 0; i < TM; i++)
        #pragma unroll
        for (int j = 0; j < TN; j++)
            g_BCp[kc][(size_t)(bm0 + ty * TM + i) * 32 + tx * TN + j] = acc[i][j];
}

__global__ void bc_reduce_kernel() {
    int idx = blockIdx.x * blockDim.x + threadIdx.x;
    if (idx >= TOK * 32) return;
    float s = 0.f;
    #pragma unroll
    for (int kc = 0; kc < KCH; kc++) s += g_BCp[kc][idx];
    g_BC[idx] = s;
}

// ---------------- causal depthwise conv (K=4) + SiLU ----------------
__global__ void conv_silu_kernel(const float* __restrict__ cw, const float* __restrict__ cb) {
    int idx = blockIdx.x * blockDim.x + threadIdx.x;
    if (idx >= TOK * DI) return;
    int token = idx / DI;
    int c = idx - token * DI;
    int b = token / L_;
    int t = token - b * L_;
    float sum = cb[c];
    #pragma unroll
    for (int k = 0; k < 4; k++) {
        int tt = t - 3 + k;
        if (tt >= 0)
            sum = fmaf(g_xz[((size_t)(b * L_ + tt)) * (2 * DI) + c], cw[c * 4 + k], sum);
    }
    float s = sum / (1.f + __expf(-sum));
    g_xconv[idx] = s;
}

// ======================================================================
//  selective scan, smem-staged & pipelined (unchanged from round 8 winner)
// ======================================================================
__global__ void __launch_bounds__(512) scan_kernel(const float* __restrict__ Dv) {
    __shared__ float s_dt[2][CH][32];
    __shared__ float s_xc[2][CH][32];
    __shared__ float s_z [2][CH][32];
    __shared__ float s_bc[2][CH][32];
    __shared__ float s_y [CH][32];

    const int tid  = threadIdx.x;
    const int warp = tid >> 5;
    const int lane = tid & 31;
    const int b    = blockIdx.x >> 6;            // 64 d-blocks per batch
    const int dblk = (blockIdx.x & 63) * 32;
    const int n    = lane & 15;
    const int dl   = 2 * warp + (lane >> 4);
    const int d    = dblk + dl;

    const float a  = g_A[d * DS + n];
    const float Dd = Dv[d];
    const size_t tok0 = (size_t)b * L_;

    float r_dt[2], r_xc[2], r_z[2], r_bc[2];

#define SCAN_LDG(t0) do { \
    _Pragma("unroll") \
    for (int e = 0; e < 2; e++) { \
        size_t tok = tok0 + (t0) + warp + 16 * e; \
        r_dt[e] = g_dt   [tok * DI + dblk + lane]; \
        r_xc[e] = g_xconv[tok * DI + dblk + lane]; \
        r_z [e] = g_xz   [tok * 2 * DI + DI + dblk + lane]; \
        r_bc[e] = g_BC   [tok * 32 + lane]; \
    } } while (0)

#define SCAN_STS(buf) do { \
    _Pragma("unroll") \
    for (int e = 0; e < 2; e++) { \
        int i = warp + 16 * e; \
        s_dt[buf][i][lane] = r_dt[e]; \
        s_xc[buf][i][lane] = r_xc[e]; \
        s_z [buf][i][lane] = r_z [e]; \
        s_bc[buf][i][lane] = r_bc[e]; \
    } } while (0)

    SCAN_LDG(0);
    SCAN_STS(0);
    __syncthreads();

    float h = 0.f;
    const int n_chunks = L_ / CH;     // 64

    for (int c = 0; c < n_chunks; c++) {
        if (c + 1 < n_chunks) SCAN_LDG((c + 1) * CH);
        const int cur = c & 1;

        #pragma unroll
        for (int i = 0; i < CH; i++) {
            float dtv = s_dt[cur][i][dl];
            float xcv = s_xc[cur][i][dl];
            float Bv  = s_bc[cur][i][n];
            float Cv  = s_bc[cur][i][16 + n];
            float e = __expf(a * dtv);
            h = fmaf(h, e, xcv * dtv * Bv);
            float p = h * Cv;
            p += __shfl_xor_sync(0xffffffffu, p, 1);
            p += __shfl_xor_sync(0xffffffffu, p, 2);
            p += __shfl_xor_sync(0xffffffffu, p, 4);
            p += __shfl_xor_sync(0xffffffffu, p, 8);
            if (n == 0) {
                float zv = s_z[cur][i][dl];
                float sig = zv / (1.f + __expf(-zv));
                s_y[i][dl] = (p + xcv * Dd) * sig;
            }
        }
        __syncthreads();   // scan reads + s_y writes done

        #pragma unroll
        for (int e = 0; e < 2; e++) {
            int i = warp + 16 * e;
            g_y[(tok0 + c * CH + i) * DI + dblk + lane] = s_y[i][lane];
        }
        if (c + 1 < n_chunks) SCAN_STS((c + 1) & 1);
        __syncthreads();   // next buffer ready; s_y drained
    }
#undef SCAN_LDG
#undef SCAN_STS
}

// ---------------- launch ----------------
extern "C" void kernel_launch(void* const* d_in, const int* in_sizes, int n_in,
                              void* d_out, int out_size) {
    const float* x      = (const float*)d_in[0];
    const float* norm_w = (const float*)d_in[1];
    const float* norm_b = (const float*)d_in[2];
    const float* W_in   = (const float*)d_in[3];
    const float* conv_w = (const float*)d_in[4];
    const float* conv_b = (const float*)d_in[5];
    const float* W_dt   = (const float*)d_in[6];
    const float* b_dt   = (const float*)d_in[7];
    const float* W_B    = (const float*)d_in[8];
    const float* W_C    = (const float*)d_in[9];
    const float* Dv     = (const float*)d_in[10];
    const float* A_log  = (const float*)d_in[11];
    const float* W_out  = (const float*)d_in[12];
    float* out = (float*)d_out;

    float *p_xn, *p_xz, *p_xc, *p_dt, *p_y;
    cudaGetSymbolAddress((void**)&p_xn, g_xn);
    cudaGetSymbolAddress((void**)&p_xz, g_xz);
    cudaGetSymbolAddress((void**)&p_xc, g_xconv);
    cudaGetSymbolAddress((void**)&p_dt, g_dt);
    cudaGetSymbolAddress((void**)&p_y,  g_y);

    // 1. layernorm
    ln_kernel<<<TOK, 256>>>(x, norm_w, norm_b, p_xn);

    // 2. in-proj: xz = xn @ W_in^T    [4096 x 4096 x 1024]
    {
        dim3 grid((2 * DI) / 128, TOK / 128);
        gemm_mma_kernel<0><<<grid, 256>>>(p_xn, W_in, p_xz, TOK, 2 * DI, DM, nullptr);
    }

    // 3. conv + silu
    conv_silu_kernel<<<(TOK * DI) / 256, 256>>>(conv_w, conv_b);

    // 4a. dt = softplus(x_conv @ W_dt^T + b_dt)   [4096 x 2048 x 2048]
    {
        dim3 grid(DI / 128, TOK / 128);
        gemm_mma_kernel<1><<<grid, 256>>>(p_xc, W_dt, p_dt, TOK, DI, DI, b_dt);
    }

    // 4b. [B|C] split-K partials + reduce
    {
        dim3 grid(KCH, TOK / 32);
        bc_partial_kernel<<<grid, 256>>>(p_xc, W_B, W_C);
        bc_reduce_kernel<<<(TOK * 32 + 255) / 256, 256>>>();
    }

    // 4c. A = -exp(A_log)
    {
        float* p_A; cudaGetSymbolAddress((void**)&p_A, g_A);
        prep_A<<<(DI * DS + 255) / 256, 256>>>(A_log, p_A);
    }

    // 5. selective scan + gating (smem-staged pipeline)
    scan_kernel<<<B_ * (DI / 32), 512>>>(Dv);

    // 6. out = residual + y @ W_out^T   [4096 x 1024 x 2048]
    {
        dim3 grid(DM / 128, TOK / 128);
        gemm_mma_kernel<2><<<grid, 256>>>(p_y, W_out, out, TOK, DM, DI, x);
    }
}

// round 10
// speedup vs baseline: 3.7040x; 1.0836x over previous
#include <cuda_runtime.h>
#include <math.h>
#include <stdint.h>

#define B_   2
#define L_   2048
#define DM   1024
#define DI   2048
#define DS   16
#define TOK  (B_*L_)
#define KCH  16            // split-K chunks for BC gemm
#define KCW  (DI / KCH)    // 128
#define CH   32            // scan time-chunk

// ---------------- scratch (device globals; no allocs allowed) ----------------
__device__ float g_xn[TOK * DM];
__device__ float g_xz[TOK * 2 * DI];
__device__ float g_xconv[TOK * DI];
__device__ float g_dt[TOK * DI];
__device__ float g_BC[TOK * 2 * DS];
__device__ float g_BCp[KCH][TOK * 2 * DS];   // split-K partials (8MB)
__device__ float g_y[TOK * DI];
__device__ float g_A[DI * DS];

// ---------------- helpers ----------------
__inline__ __device__ float warpsum(float v) {
    #pragma unroll
    for (int m = 16; m; m >>= 1) v += __shfl_xor_sync(0xffffffffu, v, m);
    return v;
}

#define RND_TF32(f) (__float_as_uint(f) + 0x1000u)   // round-to-nearest; mma ignores low 13 bits

__device__ __forceinline__ void mma_tf32(float* c, const uint32_t* a, const uint32_t* b) {
    asm volatile(
        "mma.sync.aligned.m16n8k8.row.col.f32.tf32.tf32.f32 "
        "{%0,%1,%2,%3}, {%4,%5,%6,%7}, {%8,%9}, {%0,%1,%2,%3};"
        : "+f"(c[0]), "+f"(c[1]), "+f"(c[2]), "+f"(c[3])
        : "r"(a[0]), "r"(a[1]), "r"(a[2]), "r"(a[3]), "r"(b[0]), "r"(b[1]));
}

// ======================================================================
//  mma.sync TF32 GEMM: C[M,N] = A[M,K] @ B[N,K]^T (+epilogue)
//  CTA 128x128, BK=16, 4 warps in 2x2, warp tile 64x64 (CUTLASS shape).
//  SMEM [m][k+4]: STS.128 stores, conflict-free frag LDS, 1 sync/iter.
//  EPI: 0 none, 1 softplus(v+aux[col]), 2 v+aux[row*N+col]
// ======================================================================
template<int EPI>
__global__ void __launch_bounds__(128)
gemm_mma_kernel(const float* __restrict__ A, const float* __restrict__ Bw,
                float* __restrict__ C, int M, int N, int K,
                const float* __restrict__ aux)
{
    __shared__ float As[2][128][20];
    __shared__ float Bs[2][128][20];

    const int tid  = threadIdx.x;
    const int lane = tid & 31;
    const int warp = tid >> 5;
    const int g    = lane >> 2;
    const int tig  = lane & 3;
    const int wm   = warp >> 1;          // 0..1
    const int wn   = warp & 1;           // 0..1
    const int bm0  = blockIdx.y * 128;
    const int bn0  = blockIdx.x * 128;

    float acc[4][8][4];
    #pragma unroll
    for (int i = 0; i < 4; i++)
        #pragma unroll
        for (int j = 0; j < 8; j++)
            #pragma unroll
            for (int q = 0; q < 4; q++) acc[i][j][q] = 0.f;

    const int r0 = tid >> 2;   // 0..31 (+32e)
    const int kq = tid & 3;    // k-quad: owns k = 4kq..4kq+3

    float4 ra[4], rb[4];

#define LDG_T(k0) do { \
    _Pragma("unroll") \
    for (int e = 0; e < 4; e++) { \
        ra[e] = *(const float4*)(A  + (size_t)(bm0 + r0 + 32*e) * K + (k0) + 4*kq); \
        rb[e] = *(const float4*)(Bw + (size_t)(bn0 + r0 + 32*e) * K + (k0) + 4*kq); \
    } } while (0)

#define STS_T(buf) do { \
    _Pragma("unroll") \
    for (int e = 0; e < 4; e++) { \
        uint4 u; \
        u = make_uint4(RND_TF32(ra[e].x), RND_TF32(ra[e].y), RND_TF32(ra[e].z), RND_TF32(ra[e].w)); \
        *(uint4*)&As[buf][r0 + 32*e][4*kq] = u; \
        u = make_uint4(RND_TF32(rb[e].x), RND_TF32(rb[e].y), RND_TF32(rb[e].z), RND_TF32(rb[e].w)); \
        *(uint4*)&Bs[buf][r0 + 32*e][4*kq] = u; \
    } } while (0)

    const int n_iter = K >> 4;
    LDG_T(0);
    STS_T(0);
    __syncthreads();

    for (int it = 0; it < n_iter; it++) {
        const int cur = it & 1;
        if (it + 1 < n_iter) LDG_T((it + 1) << 4);

        #pragma unroll
        for (int ks = 0; ks < 2; ks++) {
            uint32_t af[4][4], bf[8][2];
            const int k0 = ks * 8 + tig;
            const int k1 = k0 + 4;
            #pragma unroll
            for (int i = 0; i < 4; i++) {
                const int row = wm * 64 + i * 16 + g;
                af[i][0] = __float_as_uint(As[cur][row][k0]);
                af[i][1] = __float_as_uint(As[cur][row + 8][k0]);
                af[i][2] = __float_as_uint(As[cur][row][k1]);
                af[i][3] = __float_as_uint(As[cur][row + 8][k1]);
            }
            #pragma unroll
            for (int j = 0; j < 8; j++) {
                const int col = wn * 64 + j * 8 + g;
                bf[j][0] = __float_as_uint(Bs[cur][col][k0]);
                bf[j][1] = __float_as_uint(Bs[cur][col][k1]);
            }
            #pragma unroll
            for (int i = 0; i < 4; i++)
                #pragma unroll
                for (int j = 0; j < 8; j++)
                    mma_tf32(acc[i][j], af[i], bf[j]);
        }
        // STS targets the buffer whose readers finished before the previous
        // barrier -> only ONE sync per iteration needed.
        if (it + 1 < n_iter) STS_T((it + 1) & 1);
        __syncthreads();
    }

    // ---- epilogue: direct STG (float2 pairs) ----
    #pragma unroll
    for (int i = 0; i < 4; i++) {
        const int row = bm0 + wm * 64 + i * 16 + g;
        #pragma unroll
        for (int j = 0; j < 8; j++) {
            const int col = bn0 + wn * 64 + j * 8 + 2 * tig;
            #pragma unroll
            for (int half = 0; half < 2; half++) {
                const int r = row + half * 8;
                float v0 = acc[i][j][half * 2 + 0];
                float v1 = acc[i][j][half * 2 + 1];
                size_t idx = (size_t)r * N + col;
                if (EPI == 1) {
                    v0 += aux[col];
                    v1 += aux[col + 1];
                    v0 = (v0 > 20.f) ? v0 : log1pf(__expf(v0));
                    v1 = (v1 > 20.f) ? v1 : log1pf(__expf(v1));
                } else if (EPI == 2) {
                    v0 += aux[idx];
                    v1 += aux[idx + 1];
                }
                *(float2*)(C + idx) = make_float2(v0, v1);
            }
        }
    }
#undef LDG_T
#undef STS_T
}

// ---------------- layernorm ----------------
__global__ void ln_kernel(const float* __restrict__ x, const float* __restrict__ w,
                          const float* __restrict__ b, float* __restrict__ out) {
    int t = blockIdx.x;
    int tid = threadIdx.x;
    const float* xr = x + (size_t)t * DM;
    float s = 0.f, sq = 0.f;
    for (int i = tid; i < DM; i += 256) { float v = xr[i]; s += v; sq += v * v; }
    s = warpsum(s); sq = warpsum(sq);
    __shared__ float sh0[8], sh1[8];
    int wi = tid >> 5, l = tid & 31;
    if (l == 0) { sh0[wi] = s; sh1[wi] = sq; }
    __syncthreads();
    if (wi == 0) {
        s  = (l < 8) ? sh0[l] : 0.f;
        sq = (l < 8) ? sh1[l] : 0.f;
        s = warpsum(s); sq = warpsum(sq);
        if (l == 0) { sh0[0] = s; sh1[0] = sq; }
    }
    __syncthreads();
    float mu  = sh0[0] * (1.f / DM);
    float var = sh1[0] * (1.f / DM) - mu * mu;
    float r = rsqrtf(var + 1e-5f);
    for (int i = tid; i < DM; i += 256)
        out[(size_t)t * DM + i] = (xr[i] - mu) * r * w[i] + b[i];
}

// ---------------- A = -exp(A_log) ----------------
__global__ void prep_A(const float* __restrict__ Al, float* __restrict__ A) {
    int i = blockIdx.x * blockDim.x + threadIdx.x;
    if (i < DI * DS) A[i] = -expf(Al[i]);
}

// ---------------- BC split-K partial: 32x32 tile over K-chunk of 128 ----------------
__global__ void __launch_bounds__(256) bc_partial_kernel(
    const float* __restrict__ A, const float* __restrict__ Bp, const float* __restrict__ Bp2)
{
    constexpr int BM = 32, BN = 32, BK = 16, TM = 2, TN = 2;
    constexpr int PAD = 4;
    __shared__ float As[BK][BM + PAD];
    __shared__ float Bs[BK][BN + PAD];
    int tid = threadIdx.x;
    int kc  = blockIdx.x;                // 0..15
    int bm0 = blockIdx.y * BM;
    int kbeg = kc * KCW;
    constexpr int TX = BN / TN;
    int tx = tid % TX;
    int ty = tid / TX;

    float acc[TM][TN] = {};
    constexpr int AF4 = BM * BK / 4;
    constexpr int BF4 = BN * BK / 4;
    constexpr int KQ  = BK / 4;

    for (int k0 = kbeg; k0 < kbeg + KCW; k0 += BK) {
        #pragma unroll
        for (int q = tid; q < AF4; q += 256) {
            int row = q / KQ, c = q % KQ;
            float4 f = *(const float4*)(A + (size_t)(bm0 + row) * DI + k0 + 4 * c);
            As[4*c+0][row] = f.x; As[4*c+1][row] = f.y;
            As[4*c+2][row] = f.z; As[4*c+3][row] = f.w;
        }
        #pragma unroll
        for (int q = tid; q < BF4; q += 256) {
            int row = q / KQ, c = q % KQ;
            const float* src = (row < 16) ? (Bp + (size_t)row * DI) : (Bp2 + (size_t)(row - 16) * DI);
            float4 f = *(const float4*)(src + k0 + 4 * c);
            Bs[4*c+0][row] = f.x; Bs[4*c+1][row] = f.y;
            Bs[4*c+2][row] = f.z; Bs[4*c+3][row] = f.w;
        }
        __syncthreads();
        #pragma unroll
        for (int k = 0; k < BK; k++) {
            float a[TM], b[TN];
            #pragma unroll
            for (int i = 0; i < TM; i++) a[i] = As[k][ty * TM + i];
            #pragma unroll
            for (int j = 0; j < TN; j++) b[j] = Bs[k][tx * TN + j];
            #pragma unroll
            for (int i = 0; i < TM; i++)
                #pragma unroll
                for (int j = 0; j < TN; j++)
                    acc[i][j] = fmaf(a[i], b[j], acc[i][j]);
        }
        __syncthreads();
    }
    #pragma unroll
    for (int i = 0; i < TM; i++)
        #pragma unroll
        for (int j = 0; j < TN; j++)
            g_BCp[kc][(size_t)(bm0 + ty * TM + i) * 32 + tx * TN + j] = acc[i][j];
}

__global__ void bc_reduce_kernel() {
    int idx = blockIdx.x * blockDim.x + threadIdx.x;
    if (idx >= TOK * 32) return;
    float s = 0.f;
    #pragma unroll
    for (int kc = 0; kc < KCH; kc++) s += g_BCp[kc][idx];
    g_BC[idx] = s;
}

// ---------------- causal depthwise conv (K=4) + SiLU ----------------
__global__ void conv_silu_kernel(const float* __restrict__ cw, const float* __restrict__ cb) {
    int idx = blockIdx.x * blockDim.x + threadIdx.x;
    if (idx >= TOK * DI) return;
    int token = idx / DI;
    int c = idx - token * DI;
    int b = token / L_;
    int t = token - b * L_;
    float sum = cb[c];
    #pragma unroll
    for (int k = 0; k < 4; k++) {
        int tt = t - 3 + k;
        if (tt >= 0)
            sum = fmaf(g_xz[((size_t)(b * L_ + tt)) * (2 * DI) + c], cw[c * 4 + k], sum);
    }
    float s = sum / (1.f + __expf(-sum));
    g_xconv[idx] = s;
}

// ======================================================================
//  selective scan, smem-staged & pipelined (unchanged winner)
// ======================================================================
__global__ void __launch_bounds__(512) scan_kernel(const float* __restrict__ Dv) {
    __shared__ float s_dt[2][CH][32];
    __shared__ float s_xc[2][CH][32];
    __shared__ float s_z [2][CH][32];
    __shared__ float s_bc[2][CH][32];
    __shared__ float s_y [CH][32];

    const int tid  = threadIdx.x;
    const int warp = tid >> 5;
    const int lane = tid & 31;
    const int b    = blockIdx.x >> 6;            // 64 d-blocks per batch
    const int dblk = (blockIdx.x & 63) * 32;
    const int n    = lane & 15;
    const int dl   = 2 * warp + (lane >> 4);
    const int d    = dblk + dl;

    const float a  = g_A[d * DS + n];
    const float Dd = Dv[d];
    const size_t tok0 = (size_t)b * L_;

    float r_dt[2], r_xc[2], r_z[2], r_bc[2];

#define SCAN_LDG(t0) do { \
    _Pragma("unroll") \
    for (int e = 0; e < 2; e++) { \
        size_t tok = tok0 + (t0) + warp + 16 * e; \
        r_dt[e] = g_dt   [tok * DI + dblk + lane]; \
        r_xc[e] = g_xconv[tok * DI + dblk + lane]; \
        r_z [e] = g_xz   [tok * 2 * DI + DI + dblk + lane]; \
        r_bc[e] = g_BC   [tok * 32 + lane]; \
    } } while (0)

#define SCAN_STS(buf) do { \
    _Pragma("unroll") \
    for (int e = 0; e < 2; e++) { \
        int i = warp + 16 * e; \
        s_dt[buf][i][lane] = r_dt[e]; \
        s_xc[buf][i][lane] = r_xc[e]; \
        s_z [buf][i][lane] = r_z [e]; \
        s_bc[buf][i][lane] = r_bc[e]; \
    } } while (0)

    SCAN_LDG(0);
    SCAN_STS(0);
    __syncthreads();

    float h = 0.f;
    const int n_chunks = L_ / CH;     // 64

    for (int c = 0; c < n_chunks; c++) {
        if (c + 1 < n_chunks) SCAN_LDG((c + 1) * CH);
        const int cur = c & 1;

        #pragma unroll
        for (int i = 0; i < CH; i++) {
            float dtv = s_dt[cur][i][dl];
            float xcv = s_xc[cur][i][dl];
            float Bv  = s_bc[cur][i][n];
            float Cv  = s_bc[cur][i][16 + n];
            float e = __expf(a * dtv);
            h = fmaf(h, e, xcv * dtv * Bv);
            float p = h * Cv;
            p += __shfl_xor_sync(0xffffffffu, p, 1);
            p += __shfl_xor_sync(0xffffffffu, p, 2);
            p += __shfl_xor_sync(0xffffffffu, p, 4);
            p += __shfl_xor_sync(0xffffffffu, p, 8);
            if (n == 0) {
                float zv = s_z[cur][i][dl];
                float sig = zv / (1.f + __expf(-zv));
                s_y[i][dl] = (p + xcv * Dd) * sig;
            }
        }
        __syncthreads();   // scan reads + s_y writes done

        #pragma unroll
        for (int e = 0; e < 2; e++) {
            int i = warp + 16 * e;
            g_y[(tok0 + c * CH + i) * DI + dblk + lane] = s_y[i][lane];
        }
        if (c + 1 < n_chunks) SCAN_STS((c + 1) & 1);
        __syncthreads();   // next buffer ready; s_y drained
    }
#undef SCAN_LDG
#undef SCAN_STS
}

// ---------------- launch ----------------
extern "C" void kernel_launch(void* const* d_in, const int* in_sizes, int n_in,
                              void* d_out, int out_size) {
    const float* x      = (const float*)d_in[0];
    const float* norm_w = (const float*)d_in[1];
    const float* norm_b = (const float*)d_in[2];
    const float* W_in   = (const float*)d_in[3];
    const float* conv_w = (const float*)d_in[4];
    const float* conv_b = (const float*)d_in[5];
    const float* W_dt   = (const float*)d_in[6];
    const float* b_dt   = (const float*)d_in[7];
    const float* W_B    = (const float*)d_in[8];
    const float* W_C    = (const float*)d_in[9];
    const float* Dv     = (const float*)d_in[10];
    const float* A_log  = (const float*)d_in[11];
    const float* W_out  = (const float*)d_in[12];
    float* out = (float*)d_out;

    float *p_xn, *p_xz, *p_xc, *p_dt, *p_y;
    cudaGetSymbolAddress((void**)&p_xn, g_xn);
    cudaGetSymbolAddress((void**)&p_xz, g_xz);
    cudaGetSymbolAddress((void**)&p_xc, g_xconv);
    cudaGetSymbolAddress((void**)&p_dt, g_dt);
    cudaGetSymbolAddress((void**)&p_y,  g_y);

    // 1. layernorm
    ln_kernel<<<TOK, 256>>>(x, norm_w, norm_b, p_xn);

    // 2. in-proj: xz = xn @ W_in^T    [4096 x 4096 x 1024]
    {
        dim3 grid((2 * DI) / 128, TOK / 128);
        gemm_mma_kernel<0><<<grid, 128>>>(p_xn, W_in, p_xz, TOK, 2 * DI, DM, nullptr);
    }

    // 3. conv + silu
    conv_silu_kernel<<<(TOK * DI) / 256, 256>>>(conv_w, conv_b);

    // 4a. dt = softplus(x_conv @ W_dt^T + b_dt)   [4096 x 2048 x 2048]
    {
        dim3 grid(DI / 128, TOK / 128);
        gemm_mma_kernel<1><<<grid, 128>>>(p_xc, W_dt, p_dt, TOK, DI, DI, b_dt);
    }

    // 4b. [B|C] split-K partials + reduce
    {
        dim3 grid(KCH, TOK / 32);
        bc_partial_kernel<<<grid, 256>>>(p_xc, W_B, W_C);
        bc_reduce_kernel<<<(TOK * 32 + 255) / 256, 256>>>();
    }

    // 4c. A = -exp(A_log)
    {
        float* p_A; cudaGetSymbolAddress((void**)&p_A, g_A);
        prep_A<<<(DI * DS + 255) / 256, 256>>>(A_log, p_A);
    }

    // 5. selective scan + gating (smem-staged pipeline)
    scan_kernel<<<B_ * (DI / 32), 512>>>(Dv);

    // 6. out = residual + y @ W_out^T   [4096 x 1024 x 2048]
    {
        dim3 grid(DM / 128, TOK / 128);
        gemm_mma_kernel<2><<<grid, 128>>>(p_y, W_out, out, TOK, DM, DI, x);
    }
}